// round 1
// baseline (speedup 1.0000x reference)
#include <cuda_runtime.h>

#define NN 50000
#define NE 800000

// Scratch (device globals — no allocation allowed in kernel_launch).
__device__ float g_Z[(size_t)NN * 144];      // per-node [9][16]: d=0..7 from nnW, d=8 from nnb
__device__ float g_agg[2][(size_t)NN * 16];  // ping-pong node features / aggregation buffers

// ---------------------------------------------------------------------------
// prep: per node n, compute Z[n][d][o] = sum_i x[n][i] * W[d][i*16+o]
// (d=8 uses nnb), and initialize agg_out[n][o] = x[n] @ rootW + bias.
// x input is either the original x (layer 0) or relu(previous agg).
// ---------------------------------------------------------------------------
__global__ void __launch_bounds__(128) prep_kernel(
    const float* __restrict__ x0, int layer,
    const float* __restrict__ nnW, const float* __restrict__ nnb,
    const float* __restrict__ rootW, const float* __restrict__ bias)
{
    __shared__ float4 sWB[576];   // [0,512): nnW (8 x 256 floats), [512,576): nnb (256 floats)
    __shared__ float4 sR[64];     // rootW (256 floats)
    __shared__ float4 sBias[4];   // bias (16 floats)

    const int tid = threadIdx.x;
    const float4* W4  = (const float4*)(nnW   + (size_t)layer * 2048);
    const float4* B4  = (const float4*)(nnb   + (size_t)layer * 256);
    const float4* R4  = (const float4*)(rootW + (size_t)layer * 256);
    const float4* Bi4 = (const float4*)(bias  + (size_t)layer * 16);

    #pragma unroll
    for (int j = tid; j < 512; j += 128) sWB[j] = W4[j];
    for (int j = tid; j < 64;  j += 128) { sWB[512 + j] = B4[j]; sR[j] = R4[j]; }
    if (tid < 4) sBias[tid] = Bi4[tid];
    __syncthreads();

    const int n = blockIdx.x * 128 + tid;
    if (n >= NN) return;

    const float* xin = (layer == 0) ? x0 : g_agg[(layer - 1) & 1];

    float x[16];
    const float4* xr = (const float4*)(xin + (size_t)n * 16);
    #pragma unroll
    for (int c = 0; c < 4; c++) {
        float4 v = xr[c];
        x[4*c+0] = v.x; x[4*c+1] = v.y; x[4*c+2] = v.z; x[4*c+3] = v.w;
    }
    if (layer) {
        #pragma unroll
        for (int i = 0; i < 16; i++) x[i] = fmaxf(x[i], 0.f);
    }

    float4* Zo = (float4*)(g_Z + (size_t)n * 144);
    #pragma unroll 1
    for (int d = 0; d < 9; d++) {
        const float4* Wd = sWB + d * 64;
        #pragma unroll
        for (int oc = 0; oc < 4; oc++) {
            float4 acc = make_float4(0.f, 0.f, 0.f, 0.f);
            #pragma unroll
            for (int i = 0; i < 16; i++) {
                float4 w = Wd[i * 4 + oc];
                acc.x = fmaf(x[i], w.x, acc.x);
                acc.y = fmaf(x[i], w.y, acc.y);
                acc.z = fmaf(x[i], w.z, acc.z);
                acc.w = fmaf(x[i], w.w, acc.w);
            }
            Zo[d * 4 + oc] = acc;
        }
    }

    // root term: agg_out[n] = x @ rootW + bias  (edge kernel atomically adds onto this)
    float4* Ao = (float4*)(g_agg[layer & 1] + (size_t)n * 16);
    #pragma unroll
    for (int oc = 0; oc < 4; oc++) {
        float4 acc = sBias[oc];
        #pragma unroll
        for (int i = 0; i < 16; i++) {
            float4 w = sR[i * 4 + oc];
            acc.x = fmaf(x[i], w.x, acc.x);
            acc.y = fmaf(x[i], w.y, acc.y);
            acc.z = fmaf(x[i], w.z, acc.z);
            acc.w = fmaf(x[i], w.w, acc.w);
        }
        Ao[oc] = acc;
    }
}

// ---------------------------------------------------------------------------
// edge: 4 threads per edge (thread q owns outputs q*4..q*4+3).
//   msg[o] = Z[src][8][o] + sum_{d<8} ea[e][d] * Z[src][d][o]
//   atomicAdd into agg[dst][o]. 64 edges per 256-thread block.
// ---------------------------------------------------------------------------
__global__ void __launch_bounds__(256) edge_kernel(
    const int* __restrict__ ei, const float* __restrict__ ea, int layer)
{
    __shared__ float s_ea[512];
    __shared__ int   s_src[64];
    __shared__ int   s_dst[64];

    const int tid = threadIdx.x;
    const int e0  = blockIdx.x * 64;

    #pragma unroll
    for (int j = tid; j < 512; j += 256) s_ea[j] = ea[(size_t)e0 * 8 + j];
    if (tid < 64)       s_src[tid]      = ei[e0 + tid];
    else if (tid < 128) s_dst[tid - 64] = ei[NE + e0 + (tid - 64)];
    __syncthreads();

    const int le  = tid >> 2;
    const int q   = tid & 3;
    const int src = s_src[le];
    const int dst = s_dst[le];

    const float4* zr = (const float4*)(g_Z + (size_t)src * 144) + q;
    float4 msg = zr[32];  // d = 8 (nnb term)
    #pragma unroll
    for (int d = 0; d < 8; d++) {
        float  c = s_ea[le * 8 + d];
        float4 z = zr[d * 4];
        msg.x = fmaf(c, z.x, msg.x);
        msg.y = fmaf(c, z.y, msg.y);
        msg.z = fmaf(c, z.z, msg.z);
        msg.w = fmaf(c, z.w, msg.w);
    }

    float* ag = g_agg[layer & 1] + (size_t)dst * 16 + q * 4;
    atomicAdd(ag + 0, msg.x);
    atomicAdd(ag + 1, msg.y);
    atomicAdd(ag + 2, msg.z);
    atomicAdd(ag + 3, msg.w);
}

// ---------------------------------------------------------------------------
// head: out[n] = relu(agg[n]) . head_W[0:16] + gf[:,n] . head_W[16:24] + head_b
// ---------------------------------------------------------------------------
__global__ void __launch_bounds__(256) head_kernel(
    const float* __restrict__ gf, const float* __restrict__ hW,
    const float* __restrict__ hb, float* __restrict__ out)
{
    const int n = blockIdx.x * 256 + threadIdx.x;
    if (n >= NN) return;

    const float4* ar = (const float4*)(g_agg[0] + (size_t)n * 16);  // layer 2 wrote buf 0
    float acc = hb[0];
    #pragma unroll
    for (int c = 0; c < 4; c++) {
        float4 v = ar[c];
        acc = fmaf(fmaxf(v.x, 0.f), hW[4*c+0], acc);
        acc = fmaf(fmaxf(v.y, 0.f), hW[4*c+1], acc);
        acc = fmaf(fmaxf(v.z, 0.f), hW[4*c+2], acc);
        acc = fmaf(fmaxf(v.w, 0.f), hW[4*c+3], acc);
    }
    #pragma unroll
    for (int g = 0; g < 8; g++)
        acc = fmaf(gf[(size_t)g * NN + n], hW[16 + g], acc);
    out[n] = acc;
}

extern "C" void kernel_launch(void* const* d_in, const int* in_sizes, int n_in,
                              void* d_out, int out_size)
{
    const float* x     = (const float*)d_in[0];
    const int*   ei    = (const int*)  d_in[1];
    const float* ea    = (const float*)d_in[2];
    const float* gf    = (const float*)d_in[3];
    const float* nnW   = (const float*)d_in[4];
    const float* nnb   = (const float*)d_in[5];
    const float* rootW = (const float*)d_in[6];
    const float* bias  = (const float*)d_in[7];
    const float* hW    = (const float*)d_in[8];
    const float* hb    = (const float*)d_in[9];
    float* out = (float*)d_out;

    for (int layer = 0; layer < 3; layer++) {
        prep_kernel<<<(NN + 127) / 128, 128>>>(x, layer, nnW, nnb, rootW, bias);
        edge_kernel<<<NE / 64, 256>>>(ei, ea, layer);
    }
    head_kernel<<<(NN + 255) / 256, 256>>>(gf, hW, hb, out);
}

// round 2
// speedup vs baseline: 1.2583x; 1.2583x over previous
#include <cuda_runtime.h>
#include <cuda_fp16.h>

#define NN 50000
#define NE 800000

// Scratch (device globals — no allocation allowed in kernel_launch).
// g_Zh: per-node [9][16] fp16 = 288 B/node (d=0..7 from nnW, d=8 from nnb).
__device__ __half2 g_Zh[(size_t)NN * 72];
__device__ float   g_agg[2][(size_t)NN * 16];  // ping-pong node feature buffers

// ---------------------------------------------------------------------------
// prep: per node n, Z[n][d][o] = sum_i x[n][i] * W[d][i*16+o] (d=8 uses nnb),
// stored fp16; agg_out[n][o] = x[n] @ rootW + bias (fp32).
// ---------------------------------------------------------------------------
__global__ void __launch_bounds__(128) prep_kernel(
    const float* __restrict__ x0, int layer,
    const float* __restrict__ nnW, const float* __restrict__ nnb,
    const float* __restrict__ rootW, const float* __restrict__ bias)
{
    __shared__ float4 sWB[576];   // [0,512): nnW (8 x 256 floats), [512,576): nnb
    __shared__ float4 sR[64];     // rootW
    __shared__ float4 sBias[4];   // bias

    const int tid = threadIdx.x;
    const float4* W4  = (const float4*)(nnW   + (size_t)layer * 2048);
    const float4* B4  = (const float4*)(nnb   + (size_t)layer * 256);
    const float4* R4  = (const float4*)(rootW + (size_t)layer * 256);
    const float4* Bi4 = (const float4*)(bias  + (size_t)layer * 16);

    #pragma unroll
    for (int j = tid; j < 512; j += 128) sWB[j] = W4[j];
    for (int j = tid; j < 64;  j += 128) { sWB[512 + j] = B4[j]; sR[j] = R4[j]; }
    if (tid < 4) sBias[tid] = Bi4[tid];
    __syncthreads();

    const int n = blockIdx.x * 128 + tid;
    if (n >= NN) return;

    const float* xin = (layer == 0) ? x0 : g_agg[(layer - 1) & 1];

    float x[16];
    const float4* xr = (const float4*)(xin + (size_t)n * 16);
    #pragma unroll
    for (int c = 0; c < 4; c++) {
        float4 v = xr[c];
        x[4*c+0] = v.x; x[4*c+1] = v.y; x[4*c+2] = v.z; x[4*c+3] = v.w;
    }
    if (layer) {
        #pragma unroll
        for (int i = 0; i < 16; i++) x[i] = fmaxf(x[i], 0.f);
    }

    float4* Zo = (float4*)(g_Zh + (size_t)n * 72);
    #pragma unroll 1
    for (int d = 0; d < 9; d++) {
        const float4* Wd = sWB + d * 64;
        float4 acc[4];
        #pragma unroll
        for (int oc = 0; oc < 4; oc++) {
            float4 a = make_float4(0.f, 0.f, 0.f, 0.f);
            #pragma unroll
            for (int i = 0; i < 16; i++) {
                float4 w = Wd[i * 4 + oc];
                a.x = fmaf(x[i], w.x, a.x);
                a.y = fmaf(x[i], w.y, a.y);
                a.z = fmaf(x[i], w.z, a.z);
                a.w = fmaf(x[i], w.w, a.w);
            }
            acc[oc] = a;
        }
        __half2 h[8];
        #pragma unroll
        for (int oc = 0; oc < 4; oc++) {
            h[2*oc+0] = __floats2half2_rn(acc[oc].x, acc[oc].y);
            h[2*oc+1] = __floats2half2_rn(acc[oc].z, acc[oc].w);
        }
        Zo[d * 2 + 0] = *(float4*)&h[0];
        Zo[d * 2 + 1] = *(float4*)&h[4];
    }

    // root term: agg_out[n] = x @ rootW + bias
    float4* Ao = (float4*)(g_agg[layer & 1] + (size_t)n * 16);
    #pragma unroll
    for (int oc = 0; oc < 4; oc++) {
        float4 acc = sBias[oc];
        #pragma unroll
        for (int i = 0; i < 16; i++) {
            float4 w = sR[i * 4 + oc];
            acc.x = fmaf(x[i], w.x, acc.x);
            acc.y = fmaf(x[i], w.y, acc.y);
            acc.z = fmaf(x[i], w.z, acc.z);
            acc.w = fmaf(x[i], w.w, acc.w);
        }
        Ao[oc] = acc;
    }
}

// ---------------------------------------------------------------------------
// edge: 2 threads per edge (thread q owns outputs q*8..q*8+7).
//   msg[o] = Z[src][8][o] + sum_{d<8} ea[e][d] * Z[src][d][o]   (Z fp16, acc fp32)
//   vectorized red.global.add.v4.f32 into agg[dst]. 128 edges / 256-thread block.
// ---------------------------------------------------------------------------
__global__ void __launch_bounds__(256) edge_kernel(
    const int* __restrict__ ei, const float* __restrict__ ea, int layer)
{
    __shared__ float4 s_ea[256];   // 128 edges x 8 floats
    __shared__ int    s_src[128];
    __shared__ int    s_dst[128];

    const int tid = threadIdx.x;
    const int e0  = blockIdx.x * 128;

    s_ea[tid] = ((const float4*)(ea + (size_t)e0 * 8))[tid];
    if (tid < 128) s_src[tid]       = ei[e0 + tid];
    else           s_dst[tid - 128] = ei[NE + e0 + (tid - 128)];
    __syncthreads();

    const int le  = tid >> 1;
    const int q   = tid & 1;
    const int src = s_src[le];
    const int dst = s_dst[le];

    const float4* zp = (const float4*)g_Zh + (size_t)src * 18 + q;

    float m[8];
    {
        float4 v = __ldcg(zp + 16);  // d = 8 (nnb term)
        const __half2* h = (const __half2*)&v;
        #pragma unroll
        for (int k = 0; k < 4; k++) {
            float2 t = __half22float2(h[k]);
            m[2*k] = t.x; m[2*k+1] = t.y;
        }
    }

    const float4 cA = s_ea[le * 2 + 0];
    const float4 cB = s_ea[le * 2 + 1];
    const float c[8] = {cA.x, cA.y, cA.z, cA.w, cB.x, cB.y, cB.z, cB.w};

    #pragma unroll
    for (int d = 0; d < 8; d++) {
        float4 v = __ldcg(zp + d * 2);
        const __half2* h = (const __half2*)&v;
        #pragma unroll
        for (int k = 0; k < 4; k++) {
            float2 t = __half22float2(h[k]);
            m[2*k]   = fmaf(c[d], t.x, m[2*k]);
            m[2*k+1] = fmaf(c[d], t.y, m[2*k+1]);
        }
    }

    float* ag = g_agg[layer & 1] + (size_t)dst * 16 + q * 8;
    asm volatile("red.global.add.v4.f32 [%0], {%1,%2,%3,%4};"
                 :: "l"(ag),     "f"(m[0]), "f"(m[1]), "f"(m[2]), "f"(m[3]) : "memory");
    asm volatile("red.global.add.v4.f32 [%0], {%1,%2,%3,%4};"
                 :: "l"(ag + 4), "f"(m[4]), "f"(m[5]), "f"(m[6]), "f"(m[7]) : "memory");
}

// ---------------------------------------------------------------------------
// head: out[n] = relu(agg[n]) . head_W[0:16] + gf[:,n] . head_W[16:24] + head_b
// ---------------------------------------------------------------------------
__global__ void __launch_bounds__(256) head_kernel(
    const float* __restrict__ gf, const float* __restrict__ hW,
    const float* __restrict__ hb, float* __restrict__ out)
{
    const int n = blockIdx.x * 256 + threadIdx.x;
    if (n >= NN) return;

    const float4* ar = (const float4*)(g_agg[0] + (size_t)n * 16);  // layer 2 wrote buf 0
    float acc = hb[0];
    #pragma unroll
    for (int c = 0; c < 4; c++) {
        float4 v = ar[c];
        acc = fmaf(fmaxf(v.x, 0.f), hW[4*c+0], acc);
        acc = fmaf(fmaxf(v.y, 0.f), hW[4*c+1], acc);
        acc = fmaf(fmaxf(v.z, 0.f), hW[4*c+2], acc);
        acc = fmaf(fmaxf(v.w, 0.f), hW[4*c+3], acc);
    }
    #pragma unroll
    for (int g = 0; g < 8; g++)
        acc = fmaf(gf[(size_t)g * NN + n], hW[16 + g], acc);
    out[n] = acc;
}

extern "C" void kernel_launch(void* const* d_in, const int* in_sizes, int n_in,
                              void* d_out, int out_size)
{
    const float* x     = (const float*)d_in[0];
    const int*   ei    = (const int*)  d_in[1];
    const float* ea    = (const float*)d_in[2];
    const float* gf    = (const float*)d_in[3];
    const float* nnW   = (const float*)d_in[4];
    const float* nnb   = (const float*)d_in[5];
    const float* rootW = (const float*)d_in[6];
    const float* bias  = (const float*)d_in[7];
    const float* hW    = (const float*)d_in[8];
    const float* hb    = (const float*)d_in[9];
    float* out = (float*)d_out;

    for (int layer = 0; layer < 3; layer++) {
        prep_kernel<<<(NN + 127) / 128, 128>>>(x, layer, nnW, nnb, rootW, bias);
        edge_kernel<<<NE / 128, 256>>>(ei, ea, layer);
    }
    head_kernel<<<(NN + 255) / 256, 256>>>(gf, hW, hb, out);
}

// round 3
// speedup vs baseline: 1.4011x; 1.1135x over previous
#include <cuda_runtime.h>
#include <cuda_fp16.h>

#define NN 50000
#define NE 800000

// Scratch (device globals — no allocation allowed in kernel_launch).
// g_Z4: per-node Z padded to 320B (20 float4): float4 index f=2d+h holds fp16
// Z[d][h*8..h*8+7], d=0..7 from nnW, d=8 from nnb; f=18,19 unused padding.
__device__ float4 g_Z4[(size_t)NN * 20];
__device__ float  g_agg[2][(size_t)NN * 16];  // ping-pong node feature buffers

// ---------------------------------------------------------------------------
// prep: per node n, Z[n][d][o] = sum_i x[n][i] * W[d][i*16+o] (d=8 uses nnb),
// stored fp16 (320B padded stride); agg_out[n] = x[n] @ rootW + bias (fp32).
// ---------------------------------------------------------------------------
__global__ void __launch_bounds__(128) prep_kernel(
    const float* __restrict__ x0, int layer,
    const float* __restrict__ nnW, const float* __restrict__ nnb,
    const float* __restrict__ rootW, const float* __restrict__ bias)
{
    __shared__ float4 sWB[576];   // [0,512): nnW (8 x 256 floats), [512,576): nnb
    __shared__ float4 sR[64];     // rootW
    __shared__ float4 sBias[4];   // bias

    const int tid = threadIdx.x;
    const float4* W4  = (const float4*)(nnW   + (size_t)layer * 2048);
    const float4* B4  = (const float4*)(nnb   + (size_t)layer * 256);
    const float4* R4  = (const float4*)(rootW + (size_t)layer * 256);
    const float4* Bi4 = (const float4*)(bias  + (size_t)layer * 16);

    #pragma unroll
    for (int j = tid; j < 512; j += 128) sWB[j] = W4[j];
    for (int j = tid; j < 64;  j += 128) { sWB[512 + j] = B4[j]; sR[j] = R4[j]; }
    if (tid < 4) sBias[tid] = Bi4[tid];
    __syncthreads();

    const int n = blockIdx.x * 128 + tid;
    if (n >= NN) return;

    const float* xin = (layer == 0) ? x0 : g_agg[(layer - 1) & 1];

    float x[16];
    const float4* xr = (const float4*)(xin + (size_t)n * 16);
    #pragma unroll
    for (int c = 0; c < 4; c++) {
        float4 v = xr[c];
        x[4*c+0] = v.x; x[4*c+1] = v.y; x[4*c+2] = v.z; x[4*c+3] = v.w;
    }
    if (layer) {
        #pragma unroll
        for (int i = 0; i < 16; i++) x[i] = fmaxf(x[i], 0.f);
    }

    float4* Zo = g_Z4 + (size_t)n * 20;
    #pragma unroll 1
    for (int d = 0; d < 9; d++) {
        const float4* Wd = sWB + d * 64;
        float4 acc[4];
        #pragma unroll
        for (int oc = 0; oc < 4; oc++) {
            float4 a = make_float4(0.f, 0.f, 0.f, 0.f);
            #pragma unroll
            for (int i = 0; i < 16; i++) {
                float4 w = Wd[i * 4 + oc];
                a.x = fmaf(x[i], w.x, a.x);
                a.y = fmaf(x[i], w.y, a.y);
                a.z = fmaf(x[i], w.z, a.z);
                a.w = fmaf(x[i], w.w, a.w);
            }
            acc[oc] = a;
        }
        __half2 h[8];
        #pragma unroll
        for (int oc = 0; oc < 4; oc++) {
            h[2*oc+0] = __floats2half2_rn(acc[oc].x, acc[oc].y);
            h[2*oc+1] = __floats2half2_rn(acc[oc].z, acc[oc].w);
        }
        Zo[d * 2 + 0] = *(float4*)&h[0];
        Zo[d * 2 + 1] = *(float4*)&h[4];
    }

    // root term: agg_out[n] = x @ rootW + bias
    float4* Ao = (float4*)(g_agg[layer & 1] + (size_t)n * 16);
    #pragma unroll
    for (int oc = 0; oc < 4; oc++) {
        float4 acc = sBias[oc];
        #pragma unroll
        for (int i = 0; i < 16; i++) {
            float4 w = sR[i * 4 + oc];
            acc.x = fmaf(x[i], w.x, acc.x);
            acc.y = fmaf(x[i], w.y, acc.y);
            acc.z = fmaf(x[i], w.z, acc.z);
            acc.w = fmaf(x[i], w.w, acc.w);
        }
        Ao[oc] = acc;
    }
}

// ---------------------------------------------------------------------------
// edge: 4 threads per edge, cooperative single-line loads.
//   Thread q loads float4 f = {q, 4+q, 8+q, 12+q} (+16+q if q<2).
//   f = 2d+h  =>  d = 2k + (q>>1), output half h = q&1.
//   Each thread accumulates its half's partials; a 4-shfl xor-2 exchange
//   gives each thread its final output QUARTER; one red.v4.f32 per thread.
// ---------------------------------------------------------------------------
__global__ void __launch_bounds__(256) edge_kernel(
    const int* __restrict__ ei, const float* __restrict__ ea, int layer)
{
    __shared__ float4 s_ea[128];   // 64 edges x 8 floats
    __shared__ int    s_src[64];
    __shared__ int    s_dst[64];

    const int tid = threadIdx.x;
    const int e0  = blockIdx.x * 64;

    if (tid < 128)      s_ea[tid]        = ((const float4*)(ea + (size_t)e0 * 8))[tid];
    else if (tid < 192) s_src[tid - 128] = ei[e0 + (tid - 128)];
    else                s_dst[tid - 192] = ei[NE + e0 + (tid - 192)];
    __syncthreads();

    const int le  = tid >> 2;
    const int q   = tid & 3;
    const int src = s_src[le];
    const int dst = s_dst[le];
    const int hi  = q >> 1;   // which quarter (sub-block of 4) this thread REDs

    const float4* zp = g_Z4 + (size_t)src * 20 + q;

    float4 v0 = __ldcg(zp + 0);
    float4 v1 = __ldcg(zp + 4);
    float4 v2 = __ldcg(zp + 8);
    float4 v3 = __ldcg(zp + 12);

    float m[8] = {0.f, 0.f, 0.f, 0.f, 0.f, 0.f, 0.f, 0.f};
    if (q < 2) {  // nnb term, d=8, coefficient 1
        float4 vb = __ldcg(zp + 16);
        const __half2* h = (const __half2*)&vb;
        #pragma unroll
        for (int k = 0; k < 4; k++) {
            float2 t = __half22float2(h[k]);
            m[2*k] = t.x; m[2*k+1] = t.y;
        }
    }

    const float4 cA = s_ea[le * 2 + 0];
    const float4 cB = s_ea[le * 2 + 1];
    const float c[8] = {cA.x, cA.y, cA.z, cA.w, cB.x, cB.y, cB.z, cB.w};

    const float4 vv[4] = {v0, v1, v2, v3};
    #pragma unroll
    for (int k = 0; k < 4; k++) {
        const float coef = c[2*k + hi];
        const __half2* h = (const __half2*)&vv[k];
        #pragma unroll
        for (int j = 0; j < 4; j++) {
            float2 t = __half22float2(h[j]);
            m[2*j]   = fmaf(coef, t.x, m[2*j]);
            m[2*j+1] = fmaf(coef, t.y, m[2*j+1]);
        }
    }

    // Cross-pair reduction (q <-> q^2 hold same half, different d's).
    // hi==0 keeps m[0..3] (sends m[4..7]); hi==1 keeps m[4..7] (sends m[0..3]).
    float r[4];
    #pragma unroll
    for (int i = 0; i < 4; i++) {
        float send = hi ? m[i] : m[4 + i];
        float recv = __shfl_xor_sync(0xffffffffu, send, 2);
        r[i] = m[hi * 4 + i] + recv;
    }

    float* ag = g_agg[layer & 1] + (size_t)dst * 16 + (q & 1) * 8 + hi * 4;
    asm volatile("red.global.add.v4.f32 [%0], {%1,%2,%3,%4};"
                 :: "l"(ag), "f"(r[0]), "f"(r[1]), "f"(r[2]), "f"(r[3]) : "memory");
}

// ---------------------------------------------------------------------------
// head: out[n] = relu(agg[n]) . head_W[0:16] + gf[:,n] . head_W[16:24] + head_b
// ---------------------------------------------------------------------------
__global__ void __launch_bounds__(256) head_kernel(
    const float* __restrict__ gf, const float* __restrict__ hW,
    const float* __restrict__ hb, float* __restrict__ out)
{
    const int n = blockIdx.x * 256 + threadIdx.x;
    if (n >= NN) return;

    const float4* ar = (const float4*)(g_agg[0] + (size_t)n * 16);  // layer 2 wrote buf 0
    float acc = hb[0];
    #pragma unroll
    for (int c = 0; c < 4; c++) {
        float4 v = ar[c];
        acc = fmaf(fmaxf(v.x, 0.f), hW[4*c+0], acc);
        acc = fmaf(fmaxf(v.y, 0.f), hW[4*c+1], acc);
        acc = fmaf(fmaxf(v.z, 0.f), hW[4*c+2], acc);
        acc = fmaf(fmaxf(v.w, 0.f), hW[4*c+3], acc);
    }
    #pragma unroll
    for (int g = 0; g < 8; g++)
        acc = fmaf(gf[(size_t)g * NN + n], hW[16 + g], acc);
    out[n] = acc;
}

extern "C" void kernel_launch(void* const* d_in, const int* in_sizes, int n_in,
                              void* d_out, int out_size)
{
    const float* x     = (const float*)d_in[0];
    const int*   ei    = (const int*)  d_in[1];
    const float* ea    = (const float*)d_in[2];
    const float* gf    = (const float*)d_in[3];
    const float* nnW   = (const float*)d_in[4];
    const float* nnb   = (const float*)d_in[5];
    const float* rootW = (const float*)d_in[6];
    const float* bias  = (const float*)d_in[7];
    const float* hW    = (const float*)d_in[8];
    const float* hb    = (const float*)d_in[9];
    float* out = (float*)d_out;

    for (int layer = 0; layer < 3; layer++) {
        prep_kernel<<<(NN + 127) / 128, 128>>>(x, layer, nnW, nnb, rootW, bias);
        edge_kernel<<<NE / 64, 256>>>(ei, ea, layer);
    }
    head_kernel<<<(NN + 255) / 256, 256>>>(gf, hW, hb, out);
}

// round 4
// speedup vs baseline: 1.4901x; 1.0635x over previous
#include <cuda_runtime.h>
#include <cuda_fp16.h>

#define NN 50000
#define NE 800000

// Scratch (device globals — no allocation allowed in kernel_launch).
// g_Z4: per-node Z padded to 320B (20 float4): float4 index f=2d+h holds fp16
// Z[d][h*8..h*8+7], d=0..7 from nnW, d=8 from nnb; f=18,19 unused padding.
__device__ float4 g_Z4[(size_t)NN * 20];
__device__ float  g_agg[2][(size_t)NN * 16];  // ping-pong node feature buffers

// ---------------------------------------------------------------------------
// prep: per node n, Z[n][d][o] = sum_i x[n][i] * W[d][i*16+o] (d=8 uses nnb),
// stored fp16 (320B padded stride); agg_out[n] = x[n] @ rootW + bias (fp32).
// ---------------------------------------------------------------------------
__global__ void __launch_bounds__(128) prep_kernel(
    const float* __restrict__ x0, int layer,
    const float* __restrict__ nnW, const float* __restrict__ nnb,
    const float* __restrict__ rootW, const float* __restrict__ bias)
{
    __shared__ float4 sWB[576];   // [0,512): nnW (8 x 256 floats), [512,576): nnb
    __shared__ float4 sR[64];     // rootW
    __shared__ float4 sBias[4];   // bias

    const int tid = threadIdx.x;
    const float4* W4  = (const float4*)(nnW   + (size_t)layer * 2048);
    const float4* B4  = (const float4*)(nnb   + (size_t)layer * 256);
    const float4* R4  = (const float4*)(rootW + (size_t)layer * 256);
    const float4* Bi4 = (const float4*)(bias  + (size_t)layer * 16);

    #pragma unroll
    for (int j = tid; j < 512; j += 128) sWB[j] = W4[j];
    for (int j = tid; j < 64;  j += 128) { sWB[512 + j] = B4[j]; sR[j] = R4[j]; }
    if (tid < 4) sBias[tid] = Bi4[tid];
    __syncthreads();

    const int n = blockIdx.x * 128 + tid;
    if (n >= NN) return;

    const float* xin = (layer == 0) ? x0 : g_agg[(layer - 1) & 1];

    float x[16];
    const float4* xr = (const float4*)(xin + (size_t)n * 16);
    #pragma unroll
    for (int c = 0; c < 4; c++) {
        float4 v = xr[c];
        x[4*c+0] = v.x; x[4*c+1] = v.y; x[4*c+2] = v.z; x[4*c+3] = v.w;
    }
    if (layer) {
        #pragma unroll
        for (int i = 0; i < 16; i++) x[i] = fmaxf(x[i], 0.f);
    }

    float4* Zo = g_Z4 + (size_t)n * 20;
    #pragma unroll 1
    for (int d = 0; d < 9; d++) {
        const float4* Wd = sWB + d * 64;
        float4 acc[4];
        #pragma unroll
        for (int oc = 0; oc < 4; oc++) {
            float4 a = make_float4(0.f, 0.f, 0.f, 0.f);
            #pragma unroll
            for (int i = 0; i < 16; i++) {
                float4 w = Wd[i * 4 + oc];
                a.x = fmaf(x[i], w.x, a.x);
                a.y = fmaf(x[i], w.y, a.y);
                a.z = fmaf(x[i], w.z, a.z);
                a.w = fmaf(x[i], w.w, a.w);
            }
            acc[oc] = a;
        }
        __half2 h[8];
        #pragma unroll
        for (int oc = 0; oc < 4; oc++) {
            h[2*oc+0] = __floats2half2_rn(acc[oc].x, acc[oc].y);
            h[2*oc+1] = __floats2half2_rn(acc[oc].z, acc[oc].w);
        }
        Zo[d * 2 + 0] = *(float4*)&h[0];
        Zo[d * 2 + 1] = *(float4*)&h[4];
    }

    // root term: agg_out[n] = x @ rootW + bias
    float4* Ao = (float4*)(g_agg[layer & 1] + (size_t)n * 16);
    #pragma unroll
    for (int oc = 0; oc < 4; oc++) {
        float4 acc = sBias[oc];
        #pragma unroll
        for (int i = 0; i < 16; i++) {
            float4 w = sR[i * 4 + oc];
            acc.x = fmaf(x[i], w.x, acc.x);
            acc.y = fmaf(x[i], w.y, acc.y);
            acc.z = fmaf(x[i], w.z, acc.z);
            acc.w = fmaf(x[i], w.w, acc.w);
        }
        Ao[oc] = acc;
    }
}

// ---------------------------------------------------------------------------
// edge: 4 threads per edge, cooperative single-line loads, fp16 HFMA2 math.
//   Thread q loads float4 f = {q, 4+q, 8+q, 12+q} (+16+q if q<2).
//   f = 2d+h => thread q covers d = 2k + (q>>1), output half h = q&1.
//   Coefficients staged in smem as broadcast half2 {c,c} (stride 9, no
//   bank conflicts). 16 HFMA2 accumulate in fp16 (acc seeded with nnb term),
//   convert 8 results to fp32, xor-2 shfl reduce, one red.v4.f32 per thread.
// ---------------------------------------------------------------------------
__global__ void __launch_bounds__(256) edge_kernel(
    const int* __restrict__ ei, const float* __restrict__ ea, int layer)
{
    __shared__ __half2 s_c[64 * 9 + 4];  // [edge][d] broadcast pairs, stride 9
    __shared__ int     s_src[64];
    __shared__ int     s_dst[64];

    const int tid = threadIdx.x;
    const int e0  = blockIdx.x * 64;

    #pragma unroll
    for (int i = 0; i < 2; i++) {
        int idx = tid + i * 256;                 // 0..511 over 64 edges x 8 dims
        float v = ea[(size_t)e0 * 8 + idx];
        s_c[(idx >> 3) * 9 + (idx & 7)] = __float2half2_rn(v);
    }
    if (tid < 64)       s_src[tid]      = ei[e0 + tid];
    else if (tid < 128) s_dst[tid - 64] = ei[NE + e0 + (tid - 64)];
    __syncthreads();

    const int le  = tid >> 2;
    const int q   = tid & 3;
    const int hi  = q >> 1;    // which d-subset / which output quarter to RED
    const int src = s_src[le];
    const int dst = s_dst[le];

    const float4* zp = g_Z4 + (size_t)src * 20 + q;

    float4 v0 = __ldcg(zp + 0);
    float4 v1 = __ldcg(zp + 4);
    float4 v2 = __ldcg(zp + 8);
    float4 v3 = __ldcg(zp + 12);

    // accumulator: nnb term (d=8, coefficient 1) for q<2, else zero
    __half2 acc[4];
    #pragma unroll
    for (int j = 0; j < 4; j++) acc[j] = __half2half2(__ushort_as_half(0));
    if (q < 2) {
        float4 vb = __ldcg(zp + 16);
        const __half2* hb = (const __half2*)&vb;
        #pragma unroll
        for (int j = 0; j < 4; j++) acc[j] = hb[j];
    }

    const __half2* cb = s_c + le * 9 + hi;  // coefficients c[2k+hi], k=0..3
    const __half2 c0 = cb[0], c1 = cb[2], c2 = cb[4], c3 = cb[6];

    const __half2* h0 = (const __half2*)&v0;
    const __half2* h1 = (const __half2*)&v1;
    const __half2* h2 = (const __half2*)&v2;
    const __half2* h3 = (const __half2*)&v3;
    #pragma unroll
    for (int j = 0; j < 4; j++) {
        acc[j] = __hfma2(c0, h0[j], acc[j]);
        acc[j] = __hfma2(c1, h1[j], acc[j]);
        acc[j] = __hfma2(c2, h2[j], acc[j]);
        acc[j] = __hfma2(c3, h3[j], acc[j]);
    }

    float m[8];
    #pragma unroll
    for (int j = 0; j < 4; j++) {
        float2 t = __half22float2(acc[j]);
        m[2*j] = t.x; m[2*j+1] = t.y;
    }

    // Cross-pair reduction (q <-> q^2: same output half q&1, different d's).
    float r[4];
    #pragma unroll
    for (int i = 0; i < 4; i++) {
        float send = hi ? m[i] : m[4 + i];
        float recv = __shfl_xor_sync(0xffffffffu, send, 2);
        r[i] = m[hi * 4 + i] + recv;
    }

    float* ag = g_agg[layer & 1] + (size_t)dst * 16 + (q & 1) * 8 + hi * 4;
    asm volatile("red.global.add.v4.f32 [%0], {%1,%2,%3,%4};"
                 :: "l"(ag), "f"(r[0]), "f"(r[1]), "f"(r[2]), "f"(r[3]) : "memory");
}

// ---------------------------------------------------------------------------
// head: out[n] = relu(agg[n]) . head_W[0:16] + gf[:,n] . head_W[16:24] + head_b
// ---------------------------------------------------------------------------
__global__ void __launch_bounds__(256) head_kernel(
    const float* __restrict__ gf, const float* __restrict__ hW,
    const float* __restrict__ hb, float* __restrict__ out)
{
    const int n = blockIdx.x * 256 + threadIdx.x;
    if (n >= NN) return;

    const float4* ar = (const float4*)(g_agg[0] + (size_t)n * 16);  // layer 2 wrote buf 0
    float acc = hb[0];
    #pragma unroll
    for (int c = 0; c < 4; c++) {
        float4 v = ar[c];
        acc = fmaf(fmaxf(v.x, 0.f), hW[4*c+0], acc);
        acc = fmaf(fmaxf(v.y, 0.f), hW[4*c+1], acc);
        acc = fmaf(fmaxf(v.z, 0.f), hW[4*c+2], acc);
        acc = fmaf(fmaxf(v.w, 0.f), hW[4*c+3], acc);
    }
    #pragma unroll
    for (int g = 0; g < 8; g++)
        acc = fmaf(gf[(size_t)g * NN + n], hW[16 + g], acc);
    out[n] = acc;
}

extern "C" void kernel_launch(void* const* d_in, const int* in_sizes, int n_in,
                              void* d_out, int out_size)
{
    const float* x     = (const float*)d_in[0];
    const int*   ei    = (const int*)  d_in[1];
    const float* ea    = (const float*)d_in[2];
    const float* gf    = (const float*)d_in[3];
    const float* nnW   = (const float*)d_in[4];
    const float* nnb   = (const float*)d_in[5];
    const float* rootW = (const float*)d_in[6];
    const float* bias  = (const float*)d_in[7];
    const float* hW    = (const float*)d_in[8];
    const float* hb    = (const float*)d_in[9];
    float* out = (float*)d_out;

    for (int layer = 0; layer < 3; layer++) {
        prep_kernel<<<(NN + 127) / 128, 128>>>(x, layer, nnW, nnb, rootW, bias);
        edge_kernel<<<NE / 64, 256>>>(ei, ea, layer);
    }
    head_kernel<<<(NN + 255) / 256, 256>>>(gf, hW, hb, out);
}